// round 10
// baseline (speedup 1.0000x reference)
#include <cuda_runtime.h>
#include <cuda_pipeline.h>
#include <math.h>

#define B 64
#define P 8732
#define M 16
#define C 81
#define EPSF 1e-7f
#define L2E 1.4426950408889634f
#define LN2 0.6931471805599453f

// ---------------- device scratch ----------------
__device__ float               g_ovl[B * P];
__device__ unsigned char       g_obj[B * P];
__device__ __align__(16) float g_conf_neg[B * P];
__device__ unsigned long long  g_best[B * M];   // packed (iou_bits<<32)|~prior_idx
__device__ int                 g_n_pos[B];
__device__ double              g_conf_pos[B];
__device__ double              g_loc_pb[B];
__device__ double              g_hard_pb[B];
__device__ unsigned int        g_done;

// ---------------- helpers ----------------
__device__ __forceinline__ float ex2f(float x) {
    float y; asm("ex2.approx.ftz.f32 %0, %1;" : "=f"(y) : "f"(x)); return y;
}
__device__ __forceinline__ float lg2f(float x) {
    float y; asm("lg2.approx.ftz.f32 %0, %1;" : "=f"(y) : "f"(x)); return y;
}

__device__ __forceinline__ double blockReduceSumD(double v) {
    __shared__ double sh[32];
    int lane = threadIdx.x & 31, wid = threadIdx.x >> 5;
    #pragma unroll
    for (int o = 16; o; o >>= 1) v += __shfl_down_sync(0xffffffffu, v, o);
    if (lane == 0) sh[wid] = v;
    __syncthreads();
    int nw = (blockDim.x + 31) >> 5;
    v = (threadIdx.x < (unsigned)nw) ? sh[threadIdx.x] : 0.0;
    if (wid == 0) {
        #pragma unroll
        for (int o = 16; o; o >>= 1) v += __shfl_down_sync(0xffffffffu, v, o);
    }
    __syncthreads();
    return v;  // valid in thread 0
}

// ---------------- K1: per-object best prior (warp per (b,m); no atomics) ----------------
#define OBJ_TPB    256
#define OBJ_GRID   (B * M / 8)       // 128 blocks, 8 warps each
#define OBJ_CHUNK  1024
__global__ void __launch_bounds__(OBJ_TPB)
k_obj(const float4* __restrict__ boxes,
      const float4* __restrict__ priors) {
    const int tid  = threadIdx.x;
    const int wid  = tid >> 5;
    const int lane = tid & 31;
    const int wg   = blockIdx.x * 8 + wid;
    const int b    = wg >> 4;
    const int m    = wg & 15;

    if (blockIdx.x == 0) {
        if (tid < B) { g_conf_pos[tid] = 0.0; g_loc_pb[tid] = 0.0; g_n_pos[tid] = 0; }
        if (tid == B) g_done = 0u;
    }

    __shared__ float4 spri[OBJ_CHUNK];

    float4 bx = boxes[b * M + m];
    float areab = (bx.z - bx.x) * (bx.w - bx.y);

    unsigned long long vmax = 0ull;
    for (int c0 = 0; c0 < P; c0 += OBJ_CHUNK) {
        int cnt = (c0 + OBJ_CHUNK <= P) ? OBJ_CHUNK : (P - c0);
        __syncthreads();
        for (int i = tid; i < cnt; i += OBJ_TPB) spri[i] = priors[c0 + i];
        __syncthreads();
        for (int j = lane; j < cnt; j += 32) {
            float4 pc = spri[j];
            float px0 = pc.x - pc.z * 0.5f;
            float py0 = pc.y - pc.w * 0.5f;
            float px1 = pc.x + pc.z * 0.5f;
            float py1 = pc.y + pc.w * 0.5f;
            float areap = (px1 - px0) * (py1 - py0);
            float iw = fmaxf(fminf(bx.z, px1) - fmaxf(bx.x, px0), 0.0f);
            float ih = fmaxf(fminf(bx.w, py1) - fmaxf(bx.y, py0), 0.0f);
            float inter = iw * ih;
            float iou = __fdividef(inter, areab + areap - inter);
            int p = c0 + j;
            unsigned long long pk =
                ((unsigned long long)__float_as_uint(iou) << 32) |
                (unsigned long long)(~(unsigned int)p);
            if (pk > vmax) vmax = pk;
        }
    }
    #pragma unroll
    for (int o = 16; o; o >>= 1) {
        unsigned long long u = __shfl_down_sync(0xffffffffu, vmax, o);
        if (u > vmax) vmax = u;
    }
    if (lane == 0) g_best[wg] = vmax;
}

// ---------------- K2: per-prior max over objects + inline scatter override ----------------
#define IOU_TPB    256
#define IOU_NCHUNK ((P + IOU_TPB - 1) / IOU_TPB)   // 35
#define IOU_GRID   (B * IOU_NCHUNK)                 // 2240
__global__ void __launch_bounds__(IOU_TPB)
k_iou(const float4* __restrict__ boxes,
      const float4* __restrict__ priors) {
    const int b     = blockIdx.x / IOU_NCHUNK;
    const int chunk = blockIdx.x % IOU_NCHUNK;
    const int tid   = threadIdx.x;
    const int p0    = chunk * IOU_TPB;
    const int p     = p0 + tid;
    const bool valid = p < P;

    __shared__ float4 sbox[M];
    __shared__ float  sarea[M];
    __shared__ unsigned long long sbest[M];
    __shared__ unsigned char sforce[IOU_TPB];
    if (tid < M) {
        float4 bx = boxes[b * M + tid];
        sbox[tid]  = bx;
        sarea[tid] = (bx.z - bx.x) * (bx.w - bx.y);
        sbest[tid] = g_best[b * M + tid];
    }
    sforce[tid] = 0;
    __syncthreads();
    if (tid == 0) {
        int j = -1;
        #pragma unroll
        for (int m = 0; m < M; m++) {
            unsigned long long v = sbest[m];
            if (v >> 32) {
                j++;
                int pp = (int)(~(unsigned int)(v & 0xffffffffull));
                if (pp >= p0 && pp < p0 + IOU_TPB) sforce[pp - p0] = (unsigned char)(j + 1);
            }
        }
    }
    __syncthreads();

    float px0 = 0.f, py0 = 0.f, px1 = 0.f, py1 = 0.f, areap = 0.f;
    if (valid) {
        float4 pc = priors[p];
        px0 = pc.x - pc.z * 0.5f;
        py0 = pc.y - pc.w * 0.5f;
        px1 = pc.x + pc.z * 0.5f;
        py1 = pc.y + pc.w * 0.5f;
        areap = (px1 - px0) * (py1 - py0);
    }

    float bv = -1.0f; int bm = 0;
    #pragma unroll
    for (int m = 0; m < M; m++) {
        float4 bx = sbox[m];
        float iw = fmaxf(fminf(bx.z, px1) - fmaxf(bx.x, px0), 0.0f);
        float ih = fmaxf(fminf(bx.w, py1) - fmaxf(bx.y, py0), 0.0f);
        float inter = iw * ih;
        float iou = __fdividef(inter, sarea[m] + areap - inter);
        if (iou > bv) { bv = iou; bm = m; }
    }
    unsigned char f = sforce[tid];
    if (f) { bv = 1.0f; bm = f - 1; }
    if (valid) {
        g_ovl[b * P + p] = bv;
        g_obj[b * P + p] = (unsigned char)bm;
    }
}

// ---------------- K3: CE loss, warp-private 8-row tiles, double-buffered, no block barriers ----------------
#define CW        8                   // warps per block
#define WROWS     8                   // rows per warp-tile
#define WTILE_F   (WROWS * C)         // 648 floats = 2592 B (16B-aligned: 648%4==0)
#define WTILE_V4  (WTILE_F / 4)       // 162
#define WNT       (B * P / WROWS)     // 69856 exact
#define WGRID     740                 // 5 blocks/SM
#define WSMEM     (CW * 2 * WTILE_F * 4)   // 41472 B

__global__ void __launch_bounds__(CW * 32, 5)
k_conf(const float4* __restrict__ scores4,
       const float4* __restrict__ locs,
       const int*    __restrict__ labels) {
    extern __shared__ float sm[];
    const int wid  = threadIdx.x >> 5;
    const int lane = threadIdx.x & 31;
    const int sub  = lane & 3;
    const int r    = lane >> 2;       // 0..7 row within warp-tile
    float* bufs[2] = { sm + wid * 2 * WTILE_F,
                       sm + wid * 2 * WTILE_F + WTILE_F };

    const int gw = blockIdx.x * CW + wid;
    const int nw = WGRID * CW;        // 5920 warps

    int t = gw;
    if (t < WNT) {
        const float4* src = scores4 + (size_t)t * WTILE_V4;
        float4* dst = (float4*)bufs[0];
        #pragma unroll
        for (int i = 0; i < 6; i++) {
            int idx = lane + i * 32;
            if (idx < WTILE_V4) __pipeline_memcpy_async(&dst[idx], &src[idx], 16);
        }
    }
    __pipeline_commit();

    int cur = 0;
    for (; t < WNT; t += nw) {
        int tn = t + nw;
        if (tn < WNT) {
            const float4* src = scores4 + (size_t)tn * WTILE_V4;
            float4* dst = (float4*)bufs[cur ^ 1];
            #pragma unroll
            for (int i = 0; i < 6; i++) {
                int idx = lane + i * 32;
                if (idx < WTILE_V4) __pipeline_memcpy_async(&dst[idx], &src[idx], 16);
            }
        }
        __pipeline_commit();
        __pipeline_wait_prior(1);     // tile t staged (this thread's copies)
        __syncwarp();                 // make all lanes' copies visible warp-wide

        const float* rp = bufs[cur] + r * C;
        // elements sub + 4i, i = 0..19 (covers 0..79); element 80 by sub==0
        float s0, s1, s2, s3;
        s0 = ex2f(rp[sub]      * L2E);
        s1 = ex2f(rp[sub + 4]  * L2E);
        s2 = ex2f(rp[sub + 8]  * L2E);
        s3 = ex2f(rp[sub + 12] * L2E);
        s0 += ex2f(rp[sub + 16] * L2E);
        s1 += ex2f(rp[sub + 20] * L2E);
        s2 += ex2f(rp[sub + 24] * L2E);
        s3 += ex2f(rp[sub + 28] * L2E);
        s0 += ex2f(rp[sub + 32] * L2E);
        s1 += ex2f(rp[sub + 36] * L2E);
        s2 += ex2f(rp[sub + 40] * L2E);
        s3 += ex2f(rp[sub + 44] * L2E);
        s0 += ex2f(rp[sub + 48] * L2E);
        s1 += ex2f(rp[sub + 52] * L2E);
        s2 += ex2f(rp[sub + 56] * L2E);
        s3 += ex2f(rp[sub + 60] * L2E);
        s0 += ex2f(rp[sub + 64] * L2E);
        s1 += ex2f(rp[sub + 68] * L2E);
        s2 += ex2f(rp[sub + 72] * L2E);
        s3 += ex2f(rp[sub + 76] * L2E);
        float s = (s0 + s1) + (s2 + s3);
        if (sub == 0) s += ex2f(rp[80] * L2E);
        s += __shfl_xor_sync(0xffffffffu, s, 1);
        s += __shfl_xor_sync(0xffffffffu, s, 2);

        if (sub == 0) {
            const int row = t * WROWS + r;
            const int b   = row / P;
            float ou = g_ovl[row];
            int   ob = (int)g_obj[row];
            int tc = (ou < 0.5f) ? 0 : labels[b * M + ob];
            float conf = lg2f(s) * LN2 - rp[tc];   // -(log_softmax[tc]) >= 0
            bool pos = tc > 0;
            g_conf_neg[row] = pos ? 0.0f : conf;
            if (pos) {
                atomicAdd(&g_conf_pos[b], (double)conf);
                atomicAdd(&g_n_pos[b], 1);
                float4 bx = locs[row];
                float iw = fmaxf(bx.z - bx.x, 0.0f);
                float ih = fmaxf(bx.w - bx.y, 0.0f);
                float inter = iw * ih;
                float area = (bx.z - bx.x) * (bx.w - bx.y);
                float iou = __fdividef(inter, area + area - inter + EPSF);
                float dious = fminf(fmaxf(iou, -1.0f), 1.0f);  // inter_diag==0 exactly
                atomicAdd(&g_loc_pb[b], (double)(1.0f - dious));
            }
        }
        __syncwarp();
        cur ^= 1;
    }
}

// ---------------- K4: per-batch top-k sum, privatized per-warp histograms (no atomics) ----------------
#define TKT 1024
#define TKW (TKT / 32)   // 32 warps
__global__ void __launch_bounds__(TKT)
k_topk(float* __restrict__ out) {
    const int b    = blockIdx.x;
    const int tid  = threadIdx.x;
    const int lane = tid & 31;
    const int wid  = tid >> 5;

    __shared__ unsigned int sv[P];          // 34928 B
    __shared__ int hist[TKW][256];          // 32768 B, one copy per warp
    __shared__ int s_bin, s_kk;
    __shared__ int s_last;

    {
        const uint4* src = (const uint4*)(g_conf_neg + b * P);
        uint4* dst = (uint4*)sv;
        for (int i = tid; i < P / 4; i += TKT) dst[i] = src[i];
    }
    __syncthreads();

    long long k = 3LL * (long long)g_n_pos[b];
    double result = 0.0;

    if (k >= P) {
        double sum = 0.0;
        for (int p = tid; p < P; p += TKT) sum += (double)__uint_as_float(sv[p]);
        result = blockReduceSumD(sum);
    } else if (k > 0) {
        unsigned int prefix = 0;
        int kk = (int)k;
        for (int pass = 3; pass >= 0; pass--) {
            const int sh_lo = pass * 8;
            // zero all private histograms
            for (int i = tid; i < TKW * 256; i += TKT) ((int*)hist)[i] = 0;
            __syncthreads();
            // histogram: warp-aggregated, plain RMW into this warp's private copy
            for (int base = 0; base < P; base += TKT) {
                int p = base + tid;
                bool in = p < P;
                unsigned int v = in ? sv[p] : 0u;
                bool match = in && (pass == 3 || (v >> (sh_lo + 8)) == prefix);
                unsigned int act = __ballot_sync(0xffffffffu, match);
                if (match) {
                    unsigned int bin = (v >> sh_lo) & 255u;
                    unsigned int peers = __match_any_sync(act, bin);
                    if ((__ffs(peers) - 1) == lane)
                        hist[wid][bin] += (int)__popc(peers);   // exclusive owner: no atomic
                }
            }
            __syncthreads();
            // combine 32 copies into hist[0][bin]
            if (tid < 256) {
                int h = 0;
                #pragma unroll
                for (int w = 0; w < TKW; w++) h += hist[w][tid];
                hist[0][tid] = h;
            }
            __syncthreads();
            // warp-0 suffix scan over 256 bins (8 bins per lane)
            if (wid == 0) {
                int base = lane * 8;
                int h0 = hist[0][base],     h1 = hist[0][base + 1];
                int h2 = hist[0][base + 2], h3 = hist[0][base + 3];
                int h4 = hist[0][base + 4], h5 = hist[0][base + 5];
                int h6 = hist[0][base + 6], h7 = hist[0][base + 7];
                int ss7 = h7;
                int ss6 = ss7 + h6, ss5 = ss6 + h5, ss4 = ss5 + h4;
                int ss3 = ss4 + h3, ss2 = ss3 + h2, ss1 = ss2 + h1;
                int ss0 = ss1 + h0;
                int S = ss0;
                #pragma unroll
                for (int off = 1; off < 32; off <<= 1) {
                    int u = __shfl_down_sync(0xffffffffu, S, off);
                    if (lane + off < 32) S += u;
                }
                int A = S - ss0;   // sum over lanes > lane
                int cge[9] = { ss0 + A, ss1 + A, ss2 + A, ss3 + A,
                               ss4 + A, ss5 + A, ss6 + A, ss7 + A, A };
                #pragma unroll
                for (int j = 0; j < 8; j++) {
                    if (cge[j] >= kk && cge[j + 1] < kk) {
                        s_bin = base + j;
                        s_kk  = kk - cge[j + 1];
                    }
                }
            }
            __syncthreads();
            prefix = (prefix << 8) | (unsigned int)s_bin;
            kk = s_kk;
        }
        unsigned int thr = prefix;
        double sum = 0.0;
        for (int p = tid; p < P; p += TKT) {
            unsigned int v = sv[p];
            if (v > thr) sum += (double)__uint_as_float(v);
        }
        result = blockReduceSumD(sum);
        if (tid == 0) result += (double)kk * (double)__uint_as_float(thr);
    }
    if (tid == 0) g_hard_pb[b] = result;

    // ---- fused final: last block combines everything ----
    __threadfence();
    if (tid == 0) {
        unsigned int t = atomicAdd(&g_done, 1u);
        s_last = (t == B - 1u) ? 1 : 0;
    }
    __syncthreads();
    if (s_last) {
        double cp = 0.0, hs = 0.0, ls = 0.0;
        long long np = 0;
        if (tid < B) {
            cp = g_conf_pos[tid];
            hs = g_hard_pb[tid];
            ls = g_loc_pb[tid];
            np = g_n_pos[tid];
        }
        double cps = blockReduceSumD(cp);
        double hss = blockReduceSumD(hs);
        double lss = blockReduceSumD(ls);
        double nps = blockReduceSumD((double)np);
        if (tid == 0) {
            float conf_loss = (float)((hss + cps) / nps);
            float loc_loss  = (float)(lss / fmax(nps, 1.0));
            out[0] = conf_loss + loc_loss;  // ALPHA = 1.0
        }
    }
}

// ---------------- launch ----------------
extern "C" void kernel_launch(void* const* d_in, const int* in_sizes, int n_in,
                              void* d_out, int out_size) {
    const float* locs   = (const float*)d_in[0];  // [B,P,4]
    const float* scores = (const float*)d_in[1];  // [B,P,C]
    const float* boxes  = (const float*)d_in[2];  // [B,M,4]
    const int*   labels = (const int*)  d_in[3];  // [B,M]
    const float* priors = (const float*)d_in[4];  // [P,4]
    float* out = (float*)d_out;

    cudaFuncSetAttribute(k_conf, cudaFuncAttributeMaxDynamicSharedMemorySize, WSMEM);

    k_obj<<<OBJ_GRID, OBJ_TPB>>>((const float4*)boxes, (const float4*)priors);
    k_iou<<<IOU_GRID, IOU_TPB>>>((const float4*)boxes, (const float4*)priors);
    k_conf<<<WGRID, CW * 32, WSMEM>>>((const float4*)scores, (const float4*)locs, labels);
    k_topk<<<B, TKT>>>(out);
}

// round 11
// speedup vs baseline: 1.0715x; 1.0715x over previous
#include <cuda_runtime.h>
#include <cuda_pipeline.h>
#include <math.h>

#define B 64
#define P 8732
#define M 16
#define C 81
#define EPSF 1e-7f
#define L2E 1.4426950408889634f
#define LN2 0.6931471805599453f

// ---------------- device scratch ----------------
__device__ __align__(16) float g_conf_neg[B * P];
__device__ unsigned long long  g_best[B * M];    // packed (iou_bits<<32)|~prior_idx
__device__ unsigned int        g_force[B * M];   // (prior<<8)|(j+1), 0 = none
__device__ int                 g_n_pos[B];
__device__ double              g_conf_pos[B];
__device__ double              g_loc_pb[B];
__device__ double              g_hard_pb[B];
__device__ unsigned int        g_done;
__device__ unsigned int        g_obj_done;

// ---------------- helpers ----------------
__device__ __forceinline__ float ex2f(float x) {
    float y; asm("ex2.approx.ftz.f32 %0, %1;" : "=f"(y) : "f"(x)); return y;
}
__device__ __forceinline__ float lg2f(float x) {
    float y; asm("lg2.approx.ftz.f32 %0, %1;" : "=f"(y) : "f"(x)); return y;
}

__device__ __forceinline__ double blockReduceSumD(double v) {
    __shared__ double sh[32];
    int lane = threadIdx.x & 31, wid = threadIdx.x >> 5;
    #pragma unroll
    for (int o = 16; o; o >>= 1) v += __shfl_down_sync(0xffffffffu, v, o);
    if (lane == 0) sh[wid] = v;
    __syncthreads();
    int nw = (blockDim.x + 31) >> 5;
    v = (threadIdx.x < (unsigned)nw) ? sh[threadIdx.x] : 0.0;
    if (wid == 0) {
        #pragma unroll
        for (int o = 16; o; o >>= 1) v += __shfl_down_sync(0xffffffffu, v, o);
    }
    __syncthreads();
    return v;  // valid in thread 0
}

// ---------------- K1: per-object best prior (warp per (b,m)); last block builds override table ----------------
#define OBJ_TPB    256
#define OBJ_GRID   (B * M / 8)       // 128 blocks, 8 warps each
#define OBJ_CHUNK  1024
__global__ void __launch_bounds__(OBJ_TPB)
k_obj(const float4* __restrict__ boxes,
      const float4* __restrict__ priors) {
    const int tid  = threadIdx.x;
    const int wid  = tid >> 5;
    const int lane = tid & 31;
    const int wg   = blockIdx.x * 8 + wid;
    const int b    = wg >> 4;
    const int m    = wg & 15;

    if (blockIdx.x == 0) {
        if (tid < B) { g_conf_pos[tid] = 0.0; g_loc_pb[tid] = 0.0; g_n_pos[tid] = 0; }
        if (tid == B) g_done = 0u;
    }

    __shared__ float4 spri[OBJ_CHUNK];
    __shared__ int s_last;

    float4 bx = boxes[b * M + m];
    float areab = (bx.z - bx.x) * (bx.w - bx.y);

    unsigned long long vmax = 0ull;
    for (int c0 = 0; c0 < P; c0 += OBJ_CHUNK) {
        int cnt = (c0 + OBJ_CHUNK <= P) ? OBJ_CHUNK : (P - c0);
        __syncthreads();
        for (int i = tid; i < cnt; i += OBJ_TPB) spri[i] = priors[c0 + i];
        __syncthreads();
        for (int j = lane; j < cnt; j += 32) {
            float4 pc = spri[j];
            float px0 = pc.x - pc.z * 0.5f;
            float py0 = pc.y - pc.w * 0.5f;
            float px1 = pc.x + pc.z * 0.5f;
            float py1 = pc.y + pc.w * 0.5f;
            float areap = (px1 - px0) * (py1 - py0);
            float iw = fmaxf(fminf(bx.z, px1) - fmaxf(bx.x, px0), 0.0f);
            float ih = fmaxf(fminf(bx.w, py1) - fmaxf(bx.y, py0), 0.0f);
            float inter = iw * ih;
            float iou = __fdividef(inter, areab + areap - inter);
            int p = c0 + j;
            unsigned long long pk =
                ((unsigned long long)__float_as_uint(iou) << 32) |
                (unsigned long long)(~(unsigned int)p);
            if (pk > vmax) vmax = pk;
        }
    }
    #pragma unroll
    for (int o = 16; o; o >>= 1) {
        unsigned long long u = __shfl_down_sync(0xffffffffu, vmax, o);
        if (u > vmax) vmax = u;
    }
    if (lane == 0) g_best[wg] = vmax;   // exclusive owner, plain store

    // ---- last block builds g_force (in-order scatter semantics + faithful j_idx) ----
    __threadfence();
    if (tid == 0) {
        unsigned int t = atomicAdd(&g_obj_done, 1u);
        s_last = (t == OBJ_GRID - 1u) ? 1 : 0;
    }
    __syncthreads();
    if (s_last) {
        if (tid < B) {
            const int bb = tid;
            int j = -1;
            #pragma unroll
            for (int mm = 0; mm < M; mm++) {
                unsigned long long v = g_best[bb * M + mm];
                unsigned int e = 0u;
                if (v >> 32) {
                    j++;
                    unsigned int pp = ~(unsigned int)(v & 0xffffffffull);
                    e = (pp << 8) | (unsigned int)(j + 1);
                }
                g_force[bb * M + mm] = e;
            }
        }
        if (tid == 0) g_obj_done = 0u;
    }
}

// ---------------- K2: CE loss + inline matcher; warp-private 8-row tiles, double-buffered ----------------
#define CW        8                   // warps per block
#define WROWS     8                   // rows per warp-tile
#define WTILE_F   (WROWS * C)         // 648 floats
#define WTILE_V4  (WTILE_F / 4)       // 162
#define WNT       (B * P / WROWS)     // 69856 exact
#define WGRID     444                 // 3 blocks/SM
#define WSMEM     (CW * 2 * WTILE_F * 4)   // 41472 B dynamic

__global__ void __launch_bounds__(CW * 32, 3)
k_conf(const float4* __restrict__ scores4,
       const float4* __restrict__ locs,
       const float4* __restrict__ boxes,
       const int*    __restrict__ labels,
       const float4* __restrict__ priors) {
    extern __shared__ float sm[];
    __shared__ float4        sbox[B * M];    // 16 KB
    __shared__ unsigned char slab[B * M];    // 1 KB
    __shared__ unsigned int  sfrc[B * M];    // 4 KB

    const int tid  = threadIdx.x;
    const int wid  = tid >> 5;
    const int lane = tid & 31;
    const int sub  = lane & 3;
    const int r    = lane >> 2;       // 0..7 row within warp-tile
    float* bufs[2] = { sm + wid * 2 * WTILE_F,
                       sm + wid * 2 * WTILE_F + WTILE_F };

    // stage tables once per block
    for (int i = tid; i < B * M; i += CW * 32) {
        sbox[i] = boxes[i];
        slab[i] = (unsigned char)labels[i];
        sfrc[i] = g_force[i];
    }
    __syncthreads();   // only block barrier in this kernel

    const int gw = blockIdx.x * CW + wid;
    const int nw = WGRID * CW;

    int t = gw;
    if (t < WNT) {
        const float4* src = scores4 + (size_t)t * WTILE_V4;
        float4* dst = (float4*)bufs[0];
        #pragma unroll
        for (int i = 0; i < 6; i++) {
            int idx = lane + i * 32;
            if (idx < WTILE_V4) __pipeline_memcpy_async(&dst[idx], &src[idx], 16);
        }
    }
    __pipeline_commit();

    int cur = 0;
    for (; t < WNT; t += nw) {
        int tn = t + nw;
        if (tn < WNT) {
            const float4* src = scores4 + (size_t)tn * WTILE_V4;
            float4* dst = (float4*)bufs[cur ^ 1];
            #pragma unroll
            for (int i = 0; i < 6; i++) {
                int idx = lane + i * 32;
                if (idx < WTILE_V4) __pipeline_memcpy_async(&dst[idx], &src[idx], 16);
            }
        }
        __pipeline_commit();

        // ---- inline matcher for this row (4 sub-threads, 4 objects each) ----
        const int row = t * WROWS + r;
        const int b   = row / P;
        const int p   = row - b * P;
        float4 pc = priors[p];
        float px0 = pc.x - pc.z * 0.5f;
        float py0 = pc.y - pc.w * 0.5f;
        float px1 = pc.x + pc.z * 0.5f;
        float py1 = pc.y + pc.w * 0.5f;
        float areap = (px1 - px0) * (py1 - py0);
        unsigned long long pk = 0ull;
        #pragma unroll
        for (int i = 0; i < 4; i++) {
            int m = sub + 4 * i;
            float4 bx = sbox[b * M + m];
            float areab = (bx.z - bx.x) * (bx.w - bx.y);
            float iw = fmaxf(fminf(bx.z, px1) - fmaxf(bx.x, px0), 0.0f);
            float ih = fmaxf(fminf(bx.w, py1) - fmaxf(bx.y, py0), 0.0f);
            float inter = iw * ih;
            float iou = __fdividef(inter, areab + areap - inter);
            unsigned long long k2 =
                ((unsigned long long)__float_as_uint(iou) << 8) |
                (unsigned long long)(15 - m);          // equal iou -> smaller m wins
            if (k2 > pk) pk = k2;
        }
        {
            unsigned long long u = __shfl_xor_sync(0xffffffffu, pk, 1);
            if (u > pk) pk = u;
            u = __shfl_xor_sync(0xffffffffu, pk, 2);
            if (u > pk) pk = u;
        }

        __pipeline_wait_prior(1);
        __syncwarp();

        const float* rp = bufs[cur] + r * C;
        float s0, s1, s2, s3;
        s0 = ex2f(rp[sub]      * L2E);
        s1 = ex2f(rp[sub + 4]  * L2E);
        s2 = ex2f(rp[sub + 8]  * L2E);
        s3 = ex2f(rp[sub + 12] * L2E);
        s0 += ex2f(rp[sub + 16] * L2E);
        s1 += ex2f(rp[sub + 20] * L2E);
        s2 += ex2f(rp[sub + 24] * L2E);
        s3 += ex2f(rp[sub + 28] * L2E);
        s0 += ex2f(rp[sub + 32] * L2E);
        s1 += ex2f(rp[sub + 36] * L2E);
        s2 += ex2f(rp[sub + 40] * L2E);
        s3 += ex2f(rp[sub + 44] * L2E);
        s0 += ex2f(rp[sub + 48] * L2E);
        s1 += ex2f(rp[sub + 52] * L2E);
        s2 += ex2f(rp[sub + 56] * L2E);
        s3 += ex2f(rp[sub + 60] * L2E);
        s0 += ex2f(rp[sub + 64] * L2E);
        s1 += ex2f(rp[sub + 68] * L2E);
        s2 += ex2f(rp[sub + 72] * L2E);
        s3 += ex2f(rp[sub + 76] * L2E);
        float s = (s0 + s1) + (s2 + s3);
        if (sub == 0) s += ex2f(rp[80] * L2E);
        s += __shfl_xor_sync(0xffffffffu, s, 1);
        s += __shfl_xor_sync(0xffffffffu, s, 2);

        if (sub == 0) {
            float bv = __uint_as_float((unsigned int)(pk >> 8));
            int   bm = 15 - (int)(pk & 0xffull);
            // override scan (in m-order: last match wins, matching sequential .at[].set)
            #pragma unroll
            for (int mm = 0; mm < M; mm++) {
                unsigned int e = sfrc[b * M + mm];
                if (e && (e >> 8) == (unsigned int)p) { bv = 1.0f; bm = (int)(e & 0xffu) - 1; }
            }
            int tc = (bv < 0.5f) ? 0 : (int)slab[b * M + bm];
            float conf = lg2f(s) * LN2 - rp[tc];   // -(log_softmax[tc]) >= 0
            bool pos = tc > 0;
            g_conf_neg[row] = pos ? 0.0f : conf;
            if (pos) {
                atomicAdd(&g_conf_pos[b], (double)conf);
                atomicAdd(&g_n_pos[b], 1);
                float4 bx = locs[row];
                float iw = fmaxf(bx.z - bx.x, 0.0f);
                float ih = fmaxf(bx.w - bx.y, 0.0f);
                float inter = iw * ih;
                float area = (bx.z - bx.x) * (bx.w - bx.y);
                float iou = __fdividef(inter, area + area - inter + EPSF);
                float dious = fminf(fmaxf(iou, -1.0f), 1.0f);  // inter_diag==0 exactly
                atomicAdd(&g_loc_pb[b], (double)(1.0f - dious));
            }
        }
        __syncwarp();
        cur ^= 1;
    }
}

// ---------------- K3: per-batch top-k sum, 3-pass (11/11/10-bit) radix select ----------------
#define TKT 1024
__global__ void __launch_bounds__(TKT)
k_topk(float* __restrict__ out) {
    const int b    = blockIdx.x;
    const int tid  = threadIdx.x;
    const int lane = tid & 31;
    const int wid  = tid >> 5;

    __shared__ unsigned int sv[P];     // 34928 B
    __shared__ int hist[2048];         // 8192 B
    __shared__ int wtot[32], wsuf[33];
    __shared__ int s_bin, s_kk;
    __shared__ int s_last;

    {
        const uint4* src = (const uint4*)(g_conf_neg + b * P);
        uint4* dst = (uint4*)sv;
        for (int i = tid; i < P / 4; i += TKT) dst[i] = src[i];
    }
    __syncthreads();

    long long k = 3LL * (long long)g_n_pos[b];
    double result = 0.0;

    if (k >= P) {
        double sum = 0.0;
        for (int p = tid; p < P; p += TKT) sum += (double)__uint_as_float(sv[p]);
        result = blockReduceSumD(sum);
    } else if (k > 0) {
        unsigned int prefix = 0;
        int kk = (int)k;
        #pragma unroll
        for (int pass = 0; pass < 3; pass++) {
            const int sh   = (pass == 0) ? 21 : (pass == 1) ? 10 : 0;
            const int bits = (pass == 2) ? 10 : 11;
            const unsigned int dmask = (1u << bits) - 1u;
            hist[tid] = 0; hist[tid + 1024] = 0;
            __syncthreads();
            for (int base = 0; base < P; base += TKT) {
                int p = base + tid;
                bool in = p < P;
                unsigned int v = in ? sv[p] : 0u;
                bool match = in && (pass == 0 || (v >> (sh + bits)) == prefix);
                unsigned int act = __ballot_sync(0xffffffffu, match);
                if (match) {
                    unsigned int bin = (v >> sh) & dmask;
                    unsigned int peers = __match_any_sync(act, bin);
                    if ((__ffs(peers) - 1) == lane)
                        atomicAdd(&hist[bin], (int)__popc(peers));
                }
            }
            __syncthreads();
            // block-wide suffix scan: thread owns bins 2*tid, 2*tid+1
            int h_lo = hist[2 * tid], h_hi = hist[2 * tid + 1];
            int tot = h_lo + h_hi;
            int v = tot;
            #pragma unroll
            for (int o = 1; o < 32; o <<= 1) {
                int u = __shfl_down_sync(0xffffffffu, v, o);
                if (lane + o < 32) v += u;
            }
            if (lane == 0) wtot[wid] = v;
            __syncthreads();
            if (wid == 0) {
                int x = wtot[lane];
                #pragma unroll
                for (int o = 1; o < 32; o <<= 1) {
                    int u = __shfl_down_sync(0xffffffffu, x, o);
                    if (lane + o < 32) x += u;
                }
                wsuf[lane] = x;
                if (lane == 0) wsuf[32] = 0;
            }
            __syncthreads();
            int after = (v - tot) + wsuf[wid + 1];   // strictly after this thread
            int cge0 = tot + after;                  // cnt >= bin 2*tid
            int cge1 = h_hi + after;                 // cnt >= bin 2*tid+1
            int cge2 = after;                        // cnt >= bin 2*tid+2
            if (cge0 >= kk && cge1 < kk) { s_bin = 2 * tid;     s_kk = kk - cge1; }
            if (cge1 >= kk && cge2 < kk) { s_bin = 2 * tid + 1; s_kk = kk - cge2; }
            __syncthreads();
            prefix = (prefix << bits) | (unsigned int)s_bin;
            kk = s_kk;
            __syncthreads();
        }
        unsigned int thr = prefix;   // exact k-th largest bit pattern
        double sum = 0.0;
        for (int p = tid; p < P; p += TKT) {
            unsigned int v = sv[p];
            if (v > thr) sum += (double)__uint_as_float(v);
        }
        result = blockReduceSumD(sum);
        if (tid == 0) result += (double)kk * (double)__uint_as_float(thr);
    }
    if (tid == 0) g_hard_pb[b] = result;

    // ---- fused final: last block combines everything ----
    __threadfence();
    if (tid == 0) {
        unsigned int t = atomicAdd(&g_done, 1u);
        s_last = (t == B - 1u) ? 1 : 0;
    }
    __syncthreads();
    if (s_last) {
        double cp = 0.0, hs = 0.0, ls = 0.0;
        long long np = 0;
        if (tid < B) {
            cp = g_conf_pos[tid];
            hs = g_hard_pb[tid];
            ls = g_loc_pb[tid];
            np = g_n_pos[tid];
        }
        double cps = blockReduceSumD(cp);
        double hss = blockReduceSumD(hs);
        double lss = blockReduceSumD(ls);
        double nps = blockReduceSumD((double)np);
        if (tid == 0) {
            float conf_loss = (float)((hss + cps) / nps);
            float loc_loss  = (float)(lss / fmax(nps, 1.0));
            out[0] = conf_loss + loc_loss;  // ALPHA = 1.0
        }
    }
}

// ---------------- launch ----------------
extern "C" void kernel_launch(void* const* d_in, const int* in_sizes, int n_in,
                              void* d_out, int out_size) {
    const float* locs   = (const float*)d_in[0];  // [B,P,4]
    const float* scores = (const float*)d_in[1];  // [B,P,C]
    const float* boxes  = (const float*)d_in[2];  // [B,M,4]
    const int*   labels = (const int*)  d_in[3];  // [B,M]
    const float* priors = (const float*)d_in[4];  // [P,4]
    float* out = (float*)d_out;

    cudaFuncSetAttribute(k_conf, cudaFuncAttributeMaxDynamicSharedMemorySize, WSMEM);

    k_obj<<<OBJ_GRID, OBJ_TPB>>>((const float4*)boxes, (const float4*)priors);
    k_conf<<<WGRID, CW * 32, WSMEM>>>((const float4*)scores, (const float4*)locs,
                                      (const float4*)boxes, labels, (const float4*)priors);
    k_topk<<<B, TKT>>>(out);
}

// round 12
// speedup vs baseline: 1.1096x; 1.0355x over previous
#include <cuda_runtime.h>
#include <cuda_pipeline.h>
#include <math.h>

#define B 64
#define P 8732
#define M 16
#define C 81
#define EPSF 1e-7f
#define L2E 1.4426950408889634f
#define LN2 0.6931471805599453f

// ---------------- device scratch ----------------
__device__ __align__(16) float g_conf_neg[B * P];
__device__ unsigned long long  g_best[B * M];    // packed (iou_bits<<32)|~prior_idx
__device__ unsigned int        g_force[B * M];   // (prior<<8)|(j+1), 0 = none
__device__ int                 g_n_pos[B];
__device__ double              g_conf_pos[B];
__device__ double              g_loc_pb[B];
__device__ double              g_hard_pb[B];
__device__ unsigned int        g_done;
__device__ unsigned int        g_obj_done;

// ---------------- helpers ----------------
__device__ __forceinline__ float ex2f(float x) {
    float y; asm("ex2.approx.ftz.f32 %0, %1;" : "=f"(y) : "f"(x)); return y;
}
__device__ __forceinline__ float lg2f(float x) {
    float y; asm("lg2.approx.ftz.f32 %0, %1;" : "=f"(y) : "f"(x)); return y;
}

__device__ __forceinline__ double blockReduceSumD(double v) {
    __shared__ double sh[32];
    int lane = threadIdx.x & 31, wid = threadIdx.x >> 5;
    #pragma unroll
    for (int o = 16; o; o >>= 1) v += __shfl_down_sync(0xffffffffu, v, o);
    if (lane == 0) sh[wid] = v;
    __syncthreads();
    int nw = (blockDim.x + 31) >> 5;
    v = (threadIdx.x < (unsigned)nw) ? sh[threadIdx.x] : 0.0;
    if (wid == 0) {
        #pragma unroll
        for (int o = 16; o; o >>= 1) v += __shfl_down_sync(0xffffffffu, v, o);
    }
    __syncthreads();
    return v;  // valid in thread 0
}

// ---------------- K1: per-object best prior (block per (b,m)); last block builds override table ----------------
#define OBJ_TPB    256
#define OBJ_GRID   (B * M)           // 1024 blocks
__global__ void __launch_bounds__(OBJ_TPB)
k_obj(const float4* __restrict__ boxes,
      const float4* __restrict__ priors) {
    const int bm   = blockIdx.x;
    const int tid  = threadIdx.x;
    const int lane = tid & 31;
    const int wid  = tid >> 5;

    if (bm == 0) {
        if (tid < B) { g_conf_pos[tid] = 0.0; g_loc_pb[tid] = 0.0; g_n_pos[tid] = 0; }
        if (tid == B) g_done = 0u;
    }

    __shared__ unsigned long long wred[OBJ_TPB / 32];
    __shared__ int s_last;

    float4 bx = __ldg(&boxes[bm]);
    float areab = (bx.z - bx.x) * (bx.w - bx.y);

    unsigned long long vmax = 0ull;
    for (int p = tid; p < P; p += OBJ_TPB) {
        float4 pc = __ldg(&priors[p]);
        float px0 = pc.x - pc.z * 0.5f;
        float py0 = pc.y - pc.w * 0.5f;
        float px1 = pc.x + pc.z * 0.5f;
        float py1 = pc.y + pc.w * 0.5f;
        float areap = (px1 - px0) * (py1 - py0);
        float iw = fmaxf(fminf(bx.z, px1) - fmaxf(bx.x, px0), 0.0f);
        float ih = fmaxf(fminf(bx.w, py1) - fmaxf(bx.y, py0), 0.0f);
        float inter = iw * ih;
        float iou = __fdividef(inter, areab + areap - inter);
        unsigned long long pk =
            ((unsigned long long)__float_as_uint(iou) << 32) |
            (unsigned long long)(~(unsigned int)p);      // ties -> smallest p
        if (pk > vmax) vmax = pk;
    }
    #pragma unroll
    for (int o = 16; o; o >>= 1) {
        unsigned long long u = __shfl_down_sync(0xffffffffu, vmax, o);
        if (u > vmax) vmax = u;
    }
    if (lane == 0) wred[wid] = vmax;
    __syncthreads();
    if (tid == 0) {
        unsigned long long v = wred[0];
        #pragma unroll
        for (int w = 1; w < OBJ_TPB / 32; w++)
            if (wred[w] > v) v = wred[w];
        g_best[bm] = v;
    }

    // ---- last block builds g_force (in-order scatter semantics + faithful j_idx) ----
    __threadfence();
    if (tid == 0) {
        unsigned int t = atomicAdd(&g_obj_done, 1u);
        s_last = (t == OBJ_GRID - 1u) ? 1 : 0;
    }
    __syncthreads();
    if (s_last) {
        if (tid < B) {
            const int bb = tid;
            int j = -1;
            #pragma unroll
            for (int mm = 0; mm < M; mm++) {
                unsigned long long v = g_best[bb * M + mm];
                unsigned int e = 0u;
                if (v >> 32) {
                    j++;
                    unsigned int pp = ~(unsigned int)(v & 0xffffffffull);
                    e = (pp << 8) | (unsigned int)(j + 1);
                }
                g_force[bb * M + mm] = e;
            }
        }
        if (tid == 0) g_obj_done = 0u;
    }
}

// ---------------- K2: CE loss + inline matcher; warp-private 8-row tiles, double-buffered ----------------
#define CW        8                   // warps per block
#define WROWS     8                   // rows per warp-tile
#define WTILE_F   (WROWS * C)         // 648 floats
#define WTILE_V4  (WTILE_F / 4)       // 162
#define WNT       (B * P / WROWS)     // 69856 exact
#define WGRID     592                 // 4 blocks/SM
#define WSMEM     (CW * 2 * WTILE_F * 4)   // 41472 B dynamic

__global__ void __launch_bounds__(CW * 32, 4)
k_conf(const float4* __restrict__ scores4,
       const float4* __restrict__ locs,
       const float4* __restrict__ boxes,
       const int*    __restrict__ labels,
       const float4* __restrict__ priors) {
    extern __shared__ float sm[];
    __shared__ unsigned char slab[B * M];    // 1 KB
    __shared__ unsigned int  sfrc[B * M];    // 4 KB

    const int tid  = threadIdx.x;
    const int wid  = tid >> 5;
    const int lane = tid & 31;
    const int sub  = lane & 3;
    const int r    = lane >> 2;       // 0..7 row within warp-tile
    float* bufs[2] = { sm + wid * 2 * WTILE_F,
                       sm + wid * 2 * WTILE_F + WTILE_F };

    // stage small tables once per block
    for (int i = tid; i < B * M; i += CW * 32) {
        slab[i] = (unsigned char)labels[i];
        sfrc[i] = g_force[i];
    }
    __syncthreads();   // only block barrier in this kernel

    const int gw = blockIdx.x * CW + wid;
    const int nw = WGRID * CW;

    int t = gw;
    if (t < WNT) {
        const float4* src = scores4 + (size_t)t * WTILE_V4;
        float4* dst = (float4*)bufs[0];
        #pragma unroll
        for (int i = 0; i < 6; i++) {
            int idx = lane + i * 32;
            if (idx < WTILE_V4) __pipeline_memcpy_async(&dst[idx], &src[idx], 16);
        }
    }
    __pipeline_commit();

    int cur = 0;
    for (; t < WNT; t += nw) {
        int tn = t + nw;
        if (tn < WNT) {
            const float4* src = scores4 + (size_t)tn * WTILE_V4;
            float4* dst = (float4*)bufs[cur ^ 1];
            #pragma unroll
            for (int i = 0; i < 6; i++) {
                int idx = lane + i * 32;
                if (idx < WTILE_V4) __pipeline_memcpy_async(&dst[idx], &src[idx], 16);
            }
        }
        __pipeline_commit();

        // ---- inline matcher for this row (4 sub-threads, 4 objects each) ----
        const int row = t * WROWS + r;
        const int b   = row / P;
        const int p   = row - b * P;
        float4 pc = __ldg(&priors[p]);
        float px0 = pc.x - pc.z * 0.5f;
        float py0 = pc.y - pc.w * 0.5f;
        float px1 = pc.x + pc.z * 0.5f;
        float py1 = pc.y + pc.w * 0.5f;
        float areap = (px1 - px0) * (py1 - py0);
        unsigned long long pk = 0ull;
        #pragma unroll
        for (int i = 0; i < 4; i++) {
            int m = sub + 4 * i;
            float4 bx = __ldg(&boxes[b * M + m]);
            float areab = (bx.z - bx.x) * (bx.w - bx.y);
            float iw = fmaxf(fminf(bx.z, px1) - fmaxf(bx.x, px0), 0.0f);
            float ih = fmaxf(fminf(bx.w, py1) - fmaxf(bx.y, py0), 0.0f);
            float inter = iw * ih;
            float iou = __fdividef(inter, areab + areap - inter);
            unsigned long long k2 =
                ((unsigned long long)__float_as_uint(iou) << 8) |
                (unsigned long long)(15 - m);          // equal iou -> smaller m wins
            if (k2 > pk) pk = k2;
        }
        {
            unsigned long long u = __shfl_xor_sync(0xffffffffu, pk, 1);
            if (u > pk) pk = u;
            u = __shfl_xor_sync(0xffffffffu, pk, 2);
            if (u > pk) pk = u;
        }

        __pipeline_wait_prior(1);
        __syncwarp();

        const float* rp = bufs[cur] + r * C;
        float s0, s1, s2, s3;
        s0 = ex2f(rp[sub]      * L2E);
        s1 = ex2f(rp[sub + 4]  * L2E);
        s2 = ex2f(rp[sub + 8]  * L2E);
        s3 = ex2f(rp[sub + 12] * L2E);
        s0 += ex2f(rp[sub + 16] * L2E);
        s1 += ex2f(rp[sub + 20] * L2E);
        s2 += ex2f(rp[sub + 24] * L2E);
        s3 += ex2f(rp[sub + 28] * L2E);
        s0 += ex2f(rp[sub + 32] * L2E);
        s1 += ex2f(rp[sub + 36] * L2E);
        s2 += ex2f(rp[sub + 40] * L2E);
        s3 += ex2f(rp[sub + 44] * L2E);
        s0 += ex2f(rp[sub + 48] * L2E);
        s1 += ex2f(rp[sub + 52] * L2E);
        s2 += ex2f(rp[sub + 56] * L2E);
        s3 += ex2f(rp[sub + 60] * L2E);
        s0 += ex2f(rp[sub + 64] * L2E);
        s1 += ex2f(rp[sub + 68] * L2E);
        s2 += ex2f(rp[sub + 72] * L2E);
        s3 += ex2f(rp[sub + 76] * L2E);
        float s = (s0 + s1) + (s2 + s3);
        if (sub == 0) s += ex2f(rp[80] * L2E);
        s += __shfl_xor_sync(0xffffffffu, s, 1);
        s += __shfl_xor_sync(0xffffffffu, s, 2);

        if (sub == 0) {
            float bv = __uint_as_float((unsigned int)(pk >> 8));
            int   bm = 15 - (int)(pk & 0xffull);
            // override scan (in m-order: last match wins, matching sequential .at[].set)
            #pragma unroll
            for (int mm = 0; mm < M; mm++) {
                unsigned int e = sfrc[b * M + mm];
                if (e && (e >> 8) == (unsigned int)p) { bv = 1.0f; bm = (int)(e & 0xffu) - 1; }
            }
            int tc = (bv < 0.5f) ? 0 : (int)slab[b * M + bm];
            float conf = lg2f(s) * LN2 - rp[tc];   // -(log_softmax[tc]) >= 0
            bool pos = tc > 0;
            g_conf_neg[row] = pos ? 0.0f : conf;
            if (pos) {
                atomicAdd(&g_conf_pos[b], (double)conf);
                atomicAdd(&g_n_pos[b], 1);
                float4 bx = locs[row];
                float iw = fmaxf(bx.z - bx.x, 0.0f);
                float ih = fmaxf(bx.w - bx.y, 0.0f);
                float inter = iw * ih;
                float area = (bx.z - bx.x) * (bx.w - bx.y);
                float iou = __fdividef(inter, area + area - inter + EPSF);
                float dious = fminf(fmaxf(iou, -1.0f), 1.0f);  // inter_diag==0 exactly
                atomicAdd(&g_loc_pb[b], (double)(1.0f - dious));
            }
        }
        __syncwarp();
        cur ^= 1;
    }
}

// ---------------- K3: per-batch top-k sum, 3-pass (11/11/10-bit) radix select ----------------
#define TKT 1024
__global__ void __launch_bounds__(TKT)
k_topk(float* __restrict__ out) {
    const int b    = blockIdx.x;
    const int tid  = threadIdx.x;
    const int lane = tid & 31;
    const int wid  = tid >> 5;

    __shared__ unsigned int sv[P];     // 34928 B
    __shared__ int hist[2048];         // 8192 B
    __shared__ int wtot[32], wsuf[33];
    __shared__ int s_bin, s_kk;
    __shared__ int s_last;

    {
        const uint4* src = (const uint4*)(g_conf_neg + b * P);
        uint4* dst = (uint4*)sv;
        for (int i = tid; i < P / 4; i += TKT) dst[i] = src[i];
    }
    __syncthreads();

    long long k = 3LL * (long long)g_n_pos[b];
    double result = 0.0;

    if (k >= P) {
        double sum = 0.0;
        for (int p = tid; p < P; p += TKT) sum += (double)__uint_as_float(sv[p]);
        result = blockReduceSumD(sum);
    } else if (k > 0) {
        unsigned int prefix = 0;
        int kk = (int)k;
        #pragma unroll
        for (int pass = 0; pass < 3; pass++) {
            const int sh   = (pass == 0) ? 21 : (pass == 1) ? 10 : 0;
            const int bits = (pass == 2) ? 10 : 11;
            const unsigned int dmask = (1u << bits) - 1u;
            hist[tid] = 0; hist[tid + 1024] = 0;
            __syncthreads();
            for (int base = 0; base < P; base += TKT) {
                int p = base + tid;
                bool in = p < P;
                unsigned int v = in ? sv[p] : 0u;
                bool match = in && (pass == 0 || (v >> (sh + bits)) == prefix);
                unsigned int act = __ballot_sync(0xffffffffu, match);
                if (match) {
                    unsigned int bin = (v >> sh) & dmask;
                    unsigned int peers = __match_any_sync(act, bin);
                    if ((__ffs(peers) - 1) == lane)
                        atomicAdd(&hist[bin], (int)__popc(peers));
                }
            }
            __syncthreads();
            // block-wide suffix scan: thread owns bins 2*tid, 2*tid+1
            int h_lo = hist[2 * tid], h_hi = hist[2 * tid + 1];
            int tot = h_lo + h_hi;
            int v = tot;
            #pragma unroll
            for (int o = 1; o < 32; o <<= 1) {
                int u = __shfl_down_sync(0xffffffffu, v, o);
                if (lane + o < 32) v += u;
            }
            if (lane == 0) wtot[wid] = v;
            __syncthreads();
            if (wid == 0) {
                int x = wtot[lane];
                #pragma unroll
                for (int o = 1; o < 32; o <<= 1) {
                    int u = __shfl_down_sync(0xffffffffu, x, o);
                    if (lane + o < 32) x += u;
                }
                wsuf[lane] = x;
                if (lane == 0) wsuf[32] = 0;
            }
            __syncthreads();
            int after = (v - tot) + wsuf[wid + 1];   // strictly after this thread
            int cge0 = tot + after;
            int cge1 = h_hi + after;
            int cge2 = after;
            if (cge0 >= kk && cge1 < kk) { s_bin = 2 * tid;     s_kk = kk - cge1; }
            if (cge1 >= kk && cge2 < kk) { s_bin = 2 * tid + 1; s_kk = kk - cge2; }
            __syncthreads();
            prefix = (prefix << bits) | (unsigned int)s_bin;
            kk = s_kk;
            __syncthreads();
        }
        unsigned int thr = prefix;   // exact k-th largest bit pattern
        double sum = 0.0;
        for (int p = tid; p < P; p += TKT) {
            unsigned int v = sv[p];
            if (v > thr) sum += (double)__uint_as_float(v);
        }
        result = blockReduceSumD(sum);
        if (tid == 0) result += (double)kk * (double)__uint_as_float(thr);
    }
    if (tid == 0) g_hard_pb[b] = result;

    // ---- fused final: last block combines everything ----
    __threadfence();
    if (tid == 0) {
        unsigned int t = atomicAdd(&g_done, 1u);
        s_last = (t == B - 1u) ? 1 : 0;
    }
    __syncthreads();
    if (s_last) {
        double cp = 0.0, hs = 0.0, ls = 0.0;
        long long np = 0;
        if (tid < B) {
            cp = g_conf_pos[tid];
            hs = g_hard_pb[tid];
            ls = g_loc_pb[tid];
            np = g_n_pos[tid];
        }
        double cps = blockReduceSumD(cp);
        double hss = blockReduceSumD(hs);
        double lss = blockReduceSumD(ls);
        double nps = blockReduceSumD((double)np);
        if (tid == 0) {
            float conf_loss = (float)((hss + cps) / nps);
            float loc_loss  = (float)(lss / fmax(nps, 1.0));
            out[0] = conf_loss + loc_loss;  // ALPHA = 1.0
        }
    }
}

// ---------------- launch ----------------
extern "C" void kernel_launch(void* const* d_in, const int* in_sizes, int n_in,
                              void* d_out, int out_size) {
    const float* locs   = (const float*)d_in[0];  // [B,P,4]
    const float* scores = (const float*)d_in[1];  // [B,P,C]
    const float* boxes  = (const float*)d_in[2];  // [B,M,4]
    const int*   labels = (const int*)  d_in[3];  // [B,M]
    const float* priors = (const float*)d_in[4];  // [P,4]
    float* out = (float*)d_out;

    cudaFuncSetAttribute(k_conf, cudaFuncAttributeMaxDynamicSharedMemorySize, WSMEM);

    k_obj<<<OBJ_GRID, OBJ_TPB>>>((const float4*)boxes, (const float4*)priors);
    k_conf<<<WGRID, CW * 32, WSMEM>>>((const float4*)scores, (const float4*)locs,
                                      (const float4*)boxes, labels, (const float4*)priors);
    k_topk<<<B, TKT>>>(out);
}